// round 1
// baseline (speedup 1.0000x reference)
#include <cuda_runtime.h>
#include <cuda_bf16.h>
#include <cstdint>

// Problem constants (fixed by the dataset)
#define NN  50000
#define EE  800000
#define FIN 3
#define HH  256
#define GG  64
#define OUTD 24

// ---------------- scratch (device globals; no allocation allowed) -----------
__device__ float g_h0[NN * HH];
__device__ float g_h1[NN * HH];
__device__ float g_y [NN * HH];   // h @ w_rel
__device__ float g_z [NN * HH];   // h @ w_root + b
__device__ float g_agg3[NN * FIN];
__device__ float g_pooled[GG * HH];
__device__ int   g_deg[NN + 1];
__device__ int   g_rowptr[NN + 1];
__device__ int   g_cursor[NN + 1];
__device__ int   g_csr[EE];

// ---------------- CSR construction ------------------------------------------
__global__ void zero_int_kernel(int* a, int n) {
    int i = blockIdx.x * blockDim.x + threadIdx.x;
    if (i < n) a[i] = 0;
}

__global__ void count_deg_kernel(const int* __restrict__ dst, int* __restrict__ deg, int e) {
    int i = blockIdx.x * blockDim.x + threadIdx.x;
    if (i < e) atomicAdd(&deg[dst[i]], 1);
}

// single-block exclusive scan over NN elements
__global__ void scan_kernel(const int* __restrict__ deg, int* __restrict__ rowptr, int n) {
    __shared__ int sums[1024];
    int tid = threadIdx.x;
    const int CH = (n + 1023) / 1024;
    int start = tid * CH;
    int stop  = min(start + CH, n);
    int s = 0;
    for (int i = start; i < stop; i++) s += deg[i];
    sums[tid] = s;
    __syncthreads();
    // Hillis-Steele inclusive scan
    for (int off = 1; off < 1024; off <<= 1) {
        int v = (tid >= off) ? sums[tid - off] : 0;
        __syncthreads();
        sums[tid] += v;
        __syncthreads();
    }
    int run = (tid > 0) ? sums[tid - 1] : 0;
    for (int i = start; i < stop; i++) { rowptr[i] = run; run += deg[i]; }
    if (tid == 0) rowptr[n] = sums[1023];
}

__global__ void fill_csr_kernel(const int* __restrict__ src, const int* __restrict__ dst,
                                const int* __restrict__ rowptr, int* __restrict__ cursor,
                                int* __restrict__ csr, int e) {
    int i = blockIdx.x * blockDim.x + threadIdx.x;
    if (i < e) {
        int d = dst[i];
        int pos = atomicAdd(&cursor[d], 1);
        csr[rowptr[d] + pos] = src[i];
    }
}

// ---------------- layer 1 (F_IN=3 -> H) --------------------------------------
__global__ void aggx_kernel(const float* __restrict__ x,
                            const int* __restrict__ rowptr, const int* __restrict__ csr,
                            float* __restrict__ agg3, int n) {
    int i = blockIdx.x * blockDim.x + threadIdx.x;
    if (i >= n) return;
    float a0 = 0.f, a1 = 0.f, a2 = 0.f;
    int beg = rowptr[i], end = rowptr[i + 1];
    for (int e = beg; e < end; e++) {
        int s = csr[e];
        a0 += x[s * 3 + 0];
        a1 += x[s * 3 + 1];
        a2 += x[s * 3 + 2];
    }
    agg3[i * 3 + 0] = a0;
    agg3[i * 3 + 1] = a1;
    agg3[i * 3 + 2] = a2;
}

__global__ void layer1_kernel(const float* __restrict__ x, const float* __restrict__ agg3,
                              const float* __restrict__ wr, const float* __restrict__ wro,
                              const float* __restrict__ b1, float* __restrict__ h0) {
    int n = blockIdx.x;
    int j = threadIdx.x;  // 256
    __shared__ float sx[3], sa[3];
    if (j < 3) { sx[j] = x[n * 3 + j]; sa[j] = agg3[n * 3 + j]; }
    __syncthreads();
    float v = b1[j];
    #pragma unroll
    for (int f = 0; f < 3; f++)
        v += sa[f] * wr[f * HH + j] + sx[f] * wro[f * HH + j];
    h0[(size_t)n * HH + j] = fmaxf(v, 0.f);
}

// ---------------- fused dual GEMM: Y = A@B0 ; Z = A@B1 + bias ----------------
// A: M x 256, B0/B1: 256 x 256 row-major. Block tile 128x128, BK=8, 256 thr.
__global__ __launch_bounds__(256, 2)
void gemm_dual_kernel(const float* __restrict__ A,
                      const float* __restrict__ B0, const float* __restrict__ B1,
                      const float* __restrict__ bias,
                      float* __restrict__ Y, float* __restrict__ Z, int M) {
    const int K = 256;
    __shared__ float As[8][128];
    __shared__ float Bs[8][128];

    int bm = blockIdx.x * 128;
    int bn = blockIdx.y * 128;          // 0..511
    const bool second = (bn >= 256);
    const float* B = second ? B1 : B0;
    int bcol = bn & 255;

    int tid = threadIdx.x;
    int tx = tid % 16, ty = tid / 16;

    int arow  = tid >> 1;               // 0..127
    int acol  = (tid & 1) * 4;          // 0 or 4
    int brow  = tid >> 5;               // 0..7
    int bcol4 = (tid & 31) * 4;         // 0..124

    float acc[8][8];
    #pragma unroll
    for (int i = 0; i < 8; i++)
        #pragma unroll
        for (int j = 0; j < 8; j++) acc[i][j] = 0.f;

    int gr = bm + arow;
    const float* Aptr = A + (size_t)gr * K + acol;
    const float* Bptr = B + (size_t)brow * 256 + bcol + bcol4;

    for (int k0 = 0; k0 < K; k0 += 8) {
        float4 av = make_float4(0.f, 0.f, 0.f, 0.f);
        if (gr < M) av = *(const float4*)(Aptr + k0);
        As[acol + 0][arow] = av.x;
        As[acol + 1][arow] = av.y;
        As[acol + 2][arow] = av.z;
        As[acol + 3][arow] = av.w;
        float4 bv = *(const float4*)(Bptr + (size_t)k0 * 256);
        *(float4*)&Bs[brow][bcol4] = bv;
        __syncthreads();

        #pragma unroll
        for (int k = 0; k < 8; k++) {
            float a[8], b[8];
            *(float4*)&a[0] = *(const float4*)&As[k][ty * 8];
            *(float4*)&a[4] = *(const float4*)&As[k][ty * 8 + 4];
            *(float4*)&b[0] = *(const float4*)&Bs[k][tx * 8];
            *(float4*)&b[4] = *(const float4*)&Bs[k][tx * 8 + 4];
            #pragma unroll
            for (int i = 0; i < 8; i++)
                #pragma unroll
                for (int j = 0; j < 8; j++)
                    acc[i][j] += a[i] * b[j];
        }
        __syncthreads();
    }

    float* C = second ? Z : Y;
    #pragma unroll
    for (int i = 0; i < 8; i++) {
        int r = bm + ty * 8 + i;
        if (r >= M) break;
        #pragma unroll
        for (int j = 0; j < 8; j += 4) {
            int c = bcol + tx * 8 + j;
            float4 v = make_float4(acc[i][j], acc[i][j + 1], acc[i][j + 2], acc[i][j + 3]);
            if (second) {
                v.x += bias[c]; v.y += bias[c + 1]; v.z += bias[c + 2]; v.w += bias[c + 3];
            }
            *(float4*)(C + (size_t)r * 256 + c) = v;
        }
    }
}

// ---------------- aggregation: Hout = relu(gather_sum(Y) + Z) ----------------
__global__ void aggregate_relu_kernel(const float* __restrict__ Y, const float* __restrict__ Z,
                                      const int* __restrict__ rowptr, const int* __restrict__ csr,
                                      float* __restrict__ Hout, int n) {
    int warp = (blockIdx.x * blockDim.x + threadIdx.x) >> 5;
    int lane = threadIdx.x & 31;
    if (warp >= n) return;
    int beg = rowptr[warp], end = rowptr[warp + 1];
    size_t off = (size_t)warp * HH + lane * 8;
    float4 acc0 = *(const float4*)(Z + off);
    float4 acc1 = *(const float4*)(Z + off + 4);
    int e = beg;
    for (; e + 1 < end; e += 2) {
        int s0 = csr[e], s1 = csr[e + 1];
        const float4* p0 = (const float4*)(Y + (size_t)s0 * HH + lane * 8);
        const float4* p1 = (const float4*)(Y + (size_t)s1 * HH + lane * 8);
        float4 a0 = p0[0], a1 = p0[1];
        float4 b0 = p1[0], b1 = p1[1];
        acc0.x += a0.x + b0.x; acc0.y += a0.y + b0.y; acc0.z += a0.z + b0.z; acc0.w += a0.w + b0.w;
        acc1.x += a1.x + b1.x; acc1.y += a1.y + b1.y; acc1.z += a1.z + b1.z; acc1.w += a1.w + b1.w;
    }
    if (e < end) {
        int s0 = csr[e];
        const float4* p0 = (const float4*)(Y + (size_t)s0 * HH + lane * 8);
        float4 a0 = p0[0], a1 = p0[1];
        acc0.x += a0.x; acc0.y += a0.y; acc0.z += a0.z; acc0.w += a0.w;
        acc1.x += a1.x; acc1.y += a1.y; acc1.z += a1.z; acc1.w += a1.w;
    }
    acc0.x = fmaxf(acc0.x, 0.f); acc0.y = fmaxf(acc0.y, 0.f);
    acc0.z = fmaxf(acc0.z, 0.f); acc0.w = fmaxf(acc0.w, 0.f);
    acc1.x = fmaxf(acc1.x, 0.f); acc1.y = fmaxf(acc1.y, 0.f);
    acc1.z = fmaxf(acc1.z, 0.f); acc1.w = fmaxf(acc1.w, 0.f);
    *(float4*)(Hout + off)     = acc0;
    *(float4*)(Hout + off + 4) = acc1;
}

// ---------------- mean pool over sorted batch ids ----------------------------
__device__ __forceinline__ int lower_bound_dev(const int* a, int n, int key) {
    int lo = 0, hi = n;
    while (lo < hi) {
        int mid = (lo + hi) >> 1;
        if (a[mid] < key) lo = mid + 1; else hi = mid;
    }
    return lo;
}

__global__ void pool_kernel(const float* __restrict__ H, const int* __restrict__ batch,
                            float* __restrict__ pooled, int n) {
    int g = blockIdx.x;
    int j = threadIdx.x;  // 256
    __shared__ int s_lo, s_hi;
    if (j == 0) {
        s_lo = lower_bound_dev(batch, n, g);
        s_hi = lower_bound_dev(batch, n, g + 1);
    }
    __syncthreads();
    int lo = s_lo, hi = s_hi;
    float acc = 0.f;
    for (int nd = lo; nd < hi; nd++) acc += H[(size_t)nd * HH + j];
    int cnt = hi - lo;
    pooled[g * HH + j] = acc / (float)max(cnt, 1);
}

// ---------------- output head ------------------------------------------------
__global__ void head_kernel(const float* __restrict__ pooled, const float* __restrict__ w_out,
                            const float* __restrict__ b_out, float* __restrict__ out) {
    int g = blockIdx.x;
    int j = threadIdx.x;  // 32, guard 24
    if (j >= OUTD) return;
    float acc = b_out[j];
    #pragma unroll 8
    for (int k = 0; k < HH; k++)
        acc += pooled[g * HH + k] * w_out[k * OUTD + j];
    out[g * OUTD + j] = acc;
}

// ---------------- launch -----------------------------------------------------
extern "C" void kernel_launch(void* const* d_in, const int* in_sizes, int n_in,
                              void* d_out, int out_size) {
    const float* x       = (const float*)d_in[0];
    const int*   ei      = (const int*)d_in[1];
    const int*   batch   = (const int*)d_in[2];
    const float* w_rel1  = (const float*)d_in[3];
    const float* w_root1 = (const float*)d_in[4];
    const float* b1      = (const float*)d_in[5];
    const float* w_rel   = (const float*)d_in[6];   // 6 x 256 x 256
    const float* w_root  = (const float*)d_in[7];
    const float* b       = (const float*)d_in[8];   // 6 x 256
    const float* w_out   = (const float*)d_in[9];
    const float* b_out   = (const float*)d_in[10];
    float* out = (float*)d_out;

    const int* src = ei;        // edge_index[0]
    const int* dst = ei + EE;   // edge_index[1]

    float *h0, *h1, *y, *z, *agg3, *pooled;
    int *deg, *rowptr, *cursor, *csr;
    cudaGetSymbolAddress((void**)&h0, g_h0);
    cudaGetSymbolAddress((void**)&h1, g_h1);
    cudaGetSymbolAddress((void**)&y, g_y);
    cudaGetSymbolAddress((void**)&z, g_z);
    cudaGetSymbolAddress((void**)&agg3, g_agg3);
    cudaGetSymbolAddress((void**)&pooled, g_pooled);
    cudaGetSymbolAddress((void**)&deg, g_deg);
    cudaGetSymbolAddress((void**)&rowptr, g_rowptr);
    cudaGetSymbolAddress((void**)&cursor, g_cursor);
    cudaGetSymbolAddress((void**)&csr, g_csr);

    // ---- build CSR (once per launch) ----
    zero_int_kernel<<<(NN + 255) / 256, 256>>>(deg, NN);
    zero_int_kernel<<<(NN + 255) / 256, 256>>>(cursor, NN);
    count_deg_kernel<<<(EE + 255) / 256, 256>>>(dst, deg, EE);
    scan_kernel<<<1, 1024>>>(deg, rowptr, NN);
    fill_csr_kernel<<<(EE + 255) / 256, 256>>>(src, dst, rowptr, cursor, csr, EE);

    // ---- layer 1 (3 -> 256) ----
    aggx_kernel<<<(NN + 255) / 256, 256>>>(x, rowptr, csr, agg3, NN);
    layer1_kernel<<<NN, 256>>>(x, agg3, w_rel1, w_root1, b1, h0);

    // ---- layers 2..7 (256 -> 256) ----
    float* h_cur = h0;
    float* h_nxt = h1;
    dim3 ggrid((NN + 127) / 128, 4);
    for (int i = 0; i < 6; i++) {
        const float* wr  = w_rel  + (size_t)i * HH * HH;
        const float* wro = w_root + (size_t)i * HH * HH;
        const float* bb  = b + i * HH;
        gemm_dual_kernel<<<ggrid, 256>>>(h_cur, wr, wro, bb, y, z, NN);
        aggregate_relu_kernel<<<(NN * 32 + 255) / 256, 256>>>(y, z, rowptr, csr, h_nxt, NN);
        float* t = h_cur; h_cur = h_nxt; h_nxt = t;
    }

    // ---- pool + head ----
    pool_kernel<<<GG, 256>>>(h_cur, batch, pooled, NN);
    head_kernel<<<GG, 32>>>(pooled, w_out, b_out, out);
}

// round 2
// speedup vs baseline: 1.0955x; 1.0955x over previous
#include <cuda_runtime.h>
#include <cuda_bf16.h>
#include <cstdint>

// Problem constants (fixed by the dataset)
#define NN  50000
#define EE  800000
#define FIN 3
#define HH  256
#define GG  64
#define OUTD 24

// ---------------- scratch (device globals; no allocation allowed) -----------
__device__ float g_h0[NN * HH];
__device__ float g_h1[NN * HH];
__device__ float g_y [NN * HH];   // h @ w_rel
__device__ float g_z [NN * HH];   // h @ w_root + b
__device__ float g_agg3[NN * FIN];
__device__ float g_pooled[GG * HH];
__device__ int   g_deg[NN + 1];
__device__ int   g_rowptr[NN + 1];
__device__ int   g_cursor[NN + 1];
__device__ int   g_csr[EE];

// ---------------- CSR construction ------------------------------------------
__global__ void zero_int_kernel(int* a, int n) {
    int i = blockIdx.x * blockDim.x + threadIdx.x;
    if (i < n) a[i] = 0;
}

__global__ void count_deg_kernel(const int* __restrict__ dst, int* __restrict__ deg, int e) {
    int i = blockIdx.x * blockDim.x + threadIdx.x;
    if (i < e) atomicAdd(&deg[dst[i]], 1);
}

// single-block exclusive scan over NN elements
__global__ void scan_kernel(const int* __restrict__ deg, int* __restrict__ rowptr, int n) {
    __shared__ int sums[1024];
    int tid = threadIdx.x;
    const int CH = (n + 1023) / 1024;
    int start = tid * CH;
    int stop  = min(start + CH, n);
    int s = 0;
    for (int i = start; i < stop; i++) s += deg[i];
    sums[tid] = s;
    __syncthreads();
    // Hillis-Steele inclusive scan
    for (int off = 1; off < 1024; off <<= 1) {
        int v = (tid >= off) ? sums[tid - off] : 0;
        __syncthreads();
        sums[tid] += v;
        __syncthreads();
    }
    int run = (tid > 0) ? sums[tid - 1] : 0;
    for (int i = start; i < stop; i++) { rowptr[i] = run; run += deg[i]; }
    if (tid == 0) rowptr[n] = sums[1023];
}

__global__ void fill_csr_kernel(const int* __restrict__ src, const int* __restrict__ dst,
                                const int* __restrict__ rowptr, int* __restrict__ cursor,
                                int* __restrict__ csr, int e) {
    int i = blockIdx.x * blockDim.x + threadIdx.x;
    if (i < e) {
        int d = dst[i];
        int pos = atomicAdd(&cursor[d], 1);
        csr[rowptr[d] + pos] = src[i];
    }
}

// ---------------- layer 1 (F_IN=3 -> H) --------------------------------------
__global__ void aggx_kernel(const float* __restrict__ x,
                            const int* __restrict__ rowptr, const int* __restrict__ csr,
                            float* __restrict__ agg3, int n) {
    int i = blockIdx.x * blockDim.x + threadIdx.x;
    if (i >= n) return;
    float a0 = 0.f, a1 = 0.f, a2 = 0.f;
    int beg = rowptr[i], end = rowptr[i + 1];
    for (int e = beg; e < end; e++) {
        int s = csr[e];
        a0 += x[s * 3 + 0];
        a1 += x[s * 3 + 1];
        a2 += x[s * 3 + 2];
    }
    agg3[i * 3 + 0] = a0;
    agg3[i * 3 + 1] = a1;
    agg3[i * 3 + 2] = a2;
}

__global__ void layer1_kernel(const float* __restrict__ x, const float* __restrict__ agg3,
                              const float* __restrict__ wr, const float* __restrict__ wro,
                              const float* __restrict__ b1, float* __restrict__ h0) {
    int n = blockIdx.x;
    int j = threadIdx.x;  // 256
    __shared__ float sx[3], sa[3];
    if (j < 3) { sx[j] = x[n * 3 + j]; sa[j] = agg3[n * 3 + j]; }
    __syncthreads();
    float v = b1[j];
    #pragma unroll
    for (int f = 0; f < 3; f++)
        v += sa[f] * wr[f * HH + j] + sx[f] * wro[f * HH + j];
    h0[(size_t)n * HH + j] = fmaxf(v, 0.f);
}

// ---------------- packed f32x2 helpers ---------------------------------------
__device__ __forceinline__ unsigned long long pack_f32x2(float lo, float hi) {
    unsigned long long r;
    asm("mov.b64 %0, {%1, %2};" : "=l"(r) : "f"(lo), "f"(hi));
    return r;
}
__device__ __forceinline__ void unpack_f32x2(float& lo, float& hi, unsigned long long v) {
    asm("mov.b64 {%0, %1}, %2;" : "=f"(lo), "=f"(hi) : "l"(v));
}
__device__ __forceinline__ void fma_f32x2(unsigned long long& acc,
                                          unsigned long long a, unsigned long long b) {
    asm("fma.rn.f32x2 %0, %1, %2, %0;" : "+l"(acc) : "l"(a), "l"(b));
}

// ---------------- fused dual GEMM: Y = A@B0 ; Z = A@B1 + bias ----------------
// A: M x 256, B0/B1: 256 x 256 row-major. Block tile 128x128, BK=8, 256 thr.
// Inner product uses packed fma.rn.f32x2 (FFMA2) -> 2x fp32 FLOP rate.
__global__ __launch_bounds__(256, 2)
void gemm_dual_kernel(const float* __restrict__ A,
                      const float* __restrict__ B0, const float* __restrict__ B1,
                      const float* __restrict__ bias,
                      float* __restrict__ Y, float* __restrict__ Z, int M) {
    const int K = 256;
    __shared__ float As[8][128];
    __shared__ float Bs[8][128];

    int bm = blockIdx.x * 128;
    int bn = blockIdx.y * 128;          // 0..511
    const bool second = (bn >= 256);
    const float* B = second ? B1 : B0;
    int bcol = bn & 255;

    int tid = threadIdx.x;
    int tx = tid % 16, ty = tid / 16;

    int arow  = tid >> 1;               // 0..127
    int acol  = (tid & 1) * 4;          // 0 or 4
    int brow  = tid >> 5;               // 0..7
    int bcol4 = (tid & 31) * 4;         // 0..124

    unsigned long long acc2[8][4];      // 8 rows x 4 f32x2 pairs (N pairs)
    #pragma unroll
    for (int i = 0; i < 8; i++)
        #pragma unroll
        for (int j = 0; j < 4; j++) acc2[i][j] = 0ull;

    int gr = bm + arow;
    const float* Aptr = A + (size_t)gr * K + acol;
    const float* Bptr = B + (size_t)brow * 256 + bcol + bcol4;

    for (int k0 = 0; k0 < K; k0 += 8) {
        float4 av = make_float4(0.f, 0.f, 0.f, 0.f);
        if (gr < M) av = *(const float4*)(Aptr + k0);
        As[acol + 0][arow] = av.x;
        As[acol + 1][arow] = av.y;
        As[acol + 2][arow] = av.z;
        As[acol + 3][arow] = av.w;
        float4 bv = *(const float4*)(Bptr + (size_t)k0 * 256);
        *(float4*)&Bs[brow][bcol4] = bv;
        __syncthreads();

        #pragma unroll
        for (int k = 0; k < 8; k++) {
            float a[8], b[8];
            *(float4*)&a[0] = *(const float4*)&As[k][ty * 8];
            *(float4*)&a[4] = *(const float4*)&As[k][ty * 8 + 4];
            *(float4*)&b[0] = *(const float4*)&Bs[k][tx * 8];
            *(float4*)&b[4] = *(const float4*)&Bs[k][tx * 8 + 4];

            unsigned long long ad[8], b2[4];
            #pragma unroll
            for (int i = 0; i < 8; i++) ad[i] = pack_f32x2(a[i], a[i]);
            #pragma unroll
            for (int j = 0; j < 4; j++) b2[j] = pack_f32x2(b[2 * j], b[2 * j + 1]);

            #pragma unroll
            for (int i = 0; i < 8; i++)
                #pragma unroll
                for (int j = 0; j < 4; j++)
                    fma_f32x2(acc2[i][j], ad[i], b2[j]);
        }
        __syncthreads();
    }

    float* C = second ? Z : Y;
    #pragma unroll
    for (int i = 0; i < 8; i++) {
        int r = bm + ty * 8 + i;
        if (r >= M) break;
        #pragma unroll
        for (int jp = 0; jp < 4; jp += 2) {
            int c = bcol + tx * 8 + jp * 2;
            float4 v;
            unpack_f32x2(v.x, v.y, acc2[i][jp]);
            unpack_f32x2(v.z, v.w, acc2[i][jp + 1]);
            if (second) {
                v.x += bias[c]; v.y += bias[c + 1]; v.z += bias[c + 2]; v.w += bias[c + 3];
            }
            *(float4*)(C + (size_t)r * 256 + c) = v;
        }
    }
}

// ---------------- aggregation: Hout = relu(gather_sum(Y) + Z) ----------------
__global__ void aggregate_relu_kernel(const float* __restrict__ Y, const float* __restrict__ Z,
                                      const int* __restrict__ rowptr, const int* __restrict__ csr,
                                      float* __restrict__ Hout, int n) {
    int warp = (blockIdx.x * blockDim.x + threadIdx.x) >> 5;
    int lane = threadIdx.x & 31;
    if (warp >= n) return;
    int beg = rowptr[warp], end = rowptr[warp + 1];
    size_t off = (size_t)warp * HH + lane * 8;
    float4 acc0 = *(const float4*)(Z + off);
    float4 acc1 = *(const float4*)(Z + off + 4);
    int e = beg;
    for (; e + 1 < end; e += 2) {
        int s0 = csr[e], s1 = csr[e + 1];
        const float4* p0 = (const float4*)(Y + (size_t)s0 * HH + lane * 8);
        const float4* p1 = (const float4*)(Y + (size_t)s1 * HH + lane * 8);
        float4 a0 = p0[0], a1 = p0[1];
        float4 b0 = p1[0], b1 = p1[1];
        acc0.x += a0.x + b0.x; acc0.y += a0.y + b0.y; acc0.z += a0.z + b0.z; acc0.w += a0.w + b0.w;
        acc1.x += a1.x + b1.x; acc1.y += a1.y + b1.y; acc1.z += a1.z + b1.z; acc1.w += a1.w + b1.w;
    }
    if (e < end) {
        int s0 = csr[e];
        const float4* p0 = (const float4*)(Y + (size_t)s0 * HH + lane * 8);
        float4 a0 = p0[0], a1 = p0[1];
        acc0.x += a0.x; acc0.y += a0.y; acc0.z += a0.z; acc0.w += a0.w;
        acc1.x += a1.x; acc1.y += a1.y; acc1.z += a1.z; acc1.w += a1.w;
    }
    acc0.x = fmaxf(acc0.x, 0.f); acc0.y = fmaxf(acc0.y, 0.f);
    acc0.z = fmaxf(acc0.z, 0.f); acc0.w = fmaxf(acc0.w, 0.f);
    acc1.x = fmaxf(acc1.x, 0.f); acc1.y = fmaxf(acc1.y, 0.f);
    acc1.w = fmaxf(acc1.w, 0.f); acc1.z = fmaxf(acc1.z, 0.f);
    *(float4*)(Hout + off)     = acc0;
    *(float4*)(Hout + off + 4) = acc1;
}

// ---------------- mean pool over sorted batch ids ----------------------------
__device__ __forceinline__ int lower_bound_dev(const int* a, int n, int key) {
    int lo = 0, hi = n;
    while (lo < hi) {
        int mid = (lo + hi) >> 1;
        if (a[mid] < key) lo = mid + 1; else hi = mid;
    }
    return lo;
}

__global__ void pool_kernel(const float* __restrict__ H, const int* __restrict__ batch,
                            float* __restrict__ pooled, int n) {
    int g = blockIdx.x;
    int j = threadIdx.x;  // 256
    __shared__ int s_lo, s_hi;
    if (j == 0) {
        s_lo = lower_bound_dev(batch, n, g);
        s_hi = lower_bound_dev(batch, n, g + 1);
    }
    __syncthreads();
    int lo = s_lo, hi = s_hi;
    float acc = 0.f;
    for (int nd = lo; nd < hi; nd++) acc += H[(size_t)nd * HH + j];
    int cnt = hi - lo;
    pooled[g * HH + j] = acc / (float)max(cnt, 1);
}

// ---------------- output head ------------------------------------------------
__global__ void head_kernel(const float* __restrict__ pooled, const float* __restrict__ w_out,
                            const float* __restrict__ b_out, float* __restrict__ out) {
    int g = blockIdx.x;
    int j = threadIdx.x;  // 32, guard 24
    if (j >= OUTD) return;
    float acc = b_out[j];
    #pragma unroll 8
    for (int k = 0; k < HH; k++)
        acc += pooled[g * HH + k] * w_out[k * OUTD + j];
    out[g * OUTD + j] = acc;
}

// ---------------- launch -----------------------------------------------------
extern "C" void kernel_launch(void* const* d_in, const int* in_sizes, int n_in,
                              void* d_out, int out_size) {
    const float* x       = (const float*)d_in[0];
    const int*   ei      = (const int*)d_in[1];
    const int*   batch   = (const int*)d_in[2];
    const float* w_rel1  = (const float*)d_in[3];
    const float* w_root1 = (const float*)d_in[4];
    const float* b1      = (const float*)d_in[5];
    const float* w_rel   = (const float*)d_in[6];   // 6 x 256 x 256
    const float* w_root  = (const float*)d_in[7];
    const float* b       = (const float*)d_in[8];   // 6 x 256
    const float* w_out   = (const float*)d_in[9];
    const float* b_out   = (const float*)d_in[10];
    float* out = (float*)d_out;

    const int* src = ei;        // edge_index[0]
    const int* dst = ei + EE;   // edge_index[1]

    float *h0, *h1, *y, *z, *agg3, *pooled;
    int *deg, *rowptr, *cursor, *csr;
    cudaGetSymbolAddress((void**)&h0, g_h0);
    cudaGetSymbolAddress((void**)&h1, g_h1);
    cudaGetSymbolAddress((void**)&y, g_y);
    cudaGetSymbolAddress((void**)&z, g_z);
    cudaGetSymbolAddress((void**)&agg3, g_agg3);
    cudaGetSymbolAddress((void**)&pooled, g_pooled);
    cudaGetSymbolAddress((void**)&deg, g_deg);
    cudaGetSymbolAddress((void**)&rowptr, g_rowptr);
    cudaGetSymbolAddress((void**)&cursor, g_cursor);
    cudaGetSymbolAddress((void**)&csr, g_csr);

    // ---- build CSR (once per launch) ----
    zero_int_kernel<<<(NN + 255) / 256, 256>>>(deg, NN);
    zero_int_kernel<<<(NN + 255) / 256, 256>>>(cursor, NN);
    count_deg_kernel<<<(EE + 255) / 256, 256>>>(dst, deg, EE);
    scan_kernel<<<1, 1024>>>(deg, rowptr, NN);
    fill_csr_kernel<<<(EE + 255) / 256, 256>>>(src, dst, rowptr, cursor, csr, EE);

    // ---- layer 1 (3 -> 256) ----
    aggx_kernel<<<(NN + 255) / 256, 256>>>(x, rowptr, csr, agg3, NN);
    layer1_kernel<<<NN, 256>>>(x, agg3, w_rel1, w_root1, b1, h0);

    // ---- layers 2..7 (256 -> 256) ----
    float* h_cur = h0;
    float* h_nxt = h1;
    dim3 ggrid((NN + 127) / 128, 4);
    for (int i = 0; i < 6; i++) {
        const float* wr  = w_rel  + (size_t)i * HH * HH;
        const float* wro = w_root + (size_t)i * HH * HH;
        const float* bb  = b + i * HH;
        gemm_dual_kernel<<<ggrid, 256>>>(h_cur, wr, wro, bb, y, z, NN);
        aggregate_relu_kernel<<<(NN * 32 + 255) / 256, 256>>>(y, z, rowptr, csr, h_nxt, NN);
        float* t = h_cur; h_cur = h_nxt; h_nxt = t;
    }

    // ---- pool + head ----
    pool_kernel<<<GG, 256>>>(h_cur, batch, pooled, NN);
    head_kernel<<<GG, 32>>>(pooled, w_out, b_out, out);
}